// round 1
// baseline (speedup 1.0000x reference)
#include <cuda_runtime.h>
#include <cuda_bf16.h>

#define Bb  8
#define Tt  2048
#define Cc  1024
#define HSd 64
#define Mrows (Bb*Tt)

// Scratch for projected q/k/v (12 MB total) — __device__ globals per harness rules.
__device__ float g_q[Mrows*HSd];
__device__ float g_k[Mrows*HSd];
__device__ float g_v[Mrows*HSd];

// ---------------------------------------------------------------------------
// Projection: out[m][h] = sum_k in[m][k] * W[k][h]   (M=16384, K=1024, H=64)
// Block: 256 threads, 32 rows x 64 h outputs. Tiled over K in chunks of 64.
// W chunk stored transposed (pitch 68 -> conflict-free float4 reads along k).
// ---------------------------------------------------------------------------
__global__ __launch_bounds__(256)
void proj_kernel(const float* __restrict__ qv, const float* __restrict__ kv,
                 const float* __restrict__ vv,
                 const float* __restrict__ Wq, const float* __restrict__ Wk,
                 const float* __restrict__ Wv)
{
    const float* __restrict__ in;
    const float* __restrict__ W;
    float* out;
    if (blockIdx.y == 0)      { in = qv; W = Wq; out = g_q; }
    else if (blockIdx.y == 1) { in = kv; W = Wk; out = g_k; }
    else                      { in = vv; W = Wv; out = g_v; }

    __shared__ float Wst[64*68];   // transposed: Wst[h*68 + k]
    __shared__ float Is [32*68];   // Is[r*68 + k]

    const int tid  = threadIdx.x;
    const int g    = tid >> 6;     // 0..3 : row group
    const int h    = tid & 63;     // output column
    const int row0 = blockIdx.x * 32;

    float acc[8];
#pragma unroll
    for (int i = 0; i < 8; i++) acc[i] = 0.f;

    for (int k0 = 0; k0 < Cc; k0 += 64) {
        __syncthreads();   // protect smem from previous chunk's readers
#pragma unroll
        for (int t = tid; t < 64*64; t += 256) {
            int kk = t >> 6, hh = t & 63;
            Wst[hh*68 + kk] = W[(k0 + kk)*HSd + hh];
        }
#pragma unroll
        for (int t = tid; t < 32*64; t += 256) {
            int r = t >> 6, kk = t & 63;
            Is[r*68 + kk] = in[(size_t)(row0 + r)*Cc + k0 + kk];
        }
        __syncthreads();

#pragma unroll 4
        for (int k4 = 0; k4 < 64; k4 += 4) {
            float4 w = *(const float4*)&Wst[h*68 + k4];
#pragma unroll
            for (int i = 0; i < 8; i++) {
                float4 a = *(const float4*)&Is[(g*8 + i)*68 + k4];
                acc[i] = fmaf(a.x, w.x, acc[i]);
                acc[i] = fmaf(a.y, w.y, acc[i]);
                acc[i] = fmaf(a.z, w.z, acc[i]);
                acc[i] = fmaf(a.w, w.w, acc[i]);
            }
        }
    }
#pragma unroll
    for (int i = 0; i < 8; i++)
        out[(size_t)(row0 + g*8 + i)*HSd + h] = acc[i];
}

// ---------------------------------------------------------------------------
// Flash attention, causal, one 64-row Q tile per CTA.
// 256 threads as 16x16 grid; thread (ty,tx) owns a 4x4 tile of S/O:
//   rows ty*4+i, cols tx*4+j.
// XOR quad swizzle (phys_q4 = q4 ^ (row>>2)) makes all access patterns
// conflict-free with no padding -> 3 x 16 KB tiles = exactly 48 KB static.
// P (probabilities) reuses the K tile between syncs.
// ---------------------------------------------------------------------------
__device__ __forceinline__ int swz(int row, int q4) {
    return row*64 + (((q4 ^ (row >> 2)) & 15) << 2);
}

__global__ __launch_bounds__(256)
void attn_kernel(const int* __restrict__ mask, float* __restrict__ out)
{
    __shared__ float Qs[64*64];
    __shared__ float Ks[64*64];   // reused as P after S is consumed
    __shared__ float Vs[64*64];

    const int b  = blockIdx.y;
    const int qb = (gridDim.x - 1) - blockIdx.x;  // longest blocks launch first
    const int q0 = qb * 64;
    const int tid = threadIdx.x;
    const int ty  = tid >> 4;
    const int tx  = tid & 15;

    // Load Q tile (swizzled)
    const float* qsrc = g_q + ((size_t)b*Tt + q0)*HSd;
#pragma unroll
    for (int t = tid; t < 1024; t += 256) {
        int row = t >> 4, q4 = t & 15;
        *(float4*)&Qs[swz(row, q4)] = *(const float4*)(qsrc + row*64 + q4*4);
    }

    float o[4][4];
#pragma unroll
    for (int i = 0; i < 4; i++)
#pragma unroll
        for (int j = 0; j < 4; j++) o[i][j] = 0.f;
    float mrow[4], lrow[4];
#pragma unroll
    for (int i = 0; i < 4; i++) { mrow[i] = -1e30f; lrow[i] = 0.f; }

    const float scale = 0.125f;   // HS^-0.5
    const int* mptr = mask + b*Tt;

    for (int kb = 0; kb <= qb; kb++) {
        const int k0 = kb * 64;
        __syncthreads();   // previous iteration's P/V readers done
        const float* ksrc = g_k + ((size_t)b*Tt + k0)*HSd;
        const float* vsrc = g_v + ((size_t)b*Tt + k0)*HSd;
#pragma unroll
        for (int t = tid; t < 1024; t += 256) {
            int row = t >> 4, q4 = t & 15;
            *(float4*)&Ks[swz(row, q4)] = *(const float4*)(ksrc + row*64 + q4*4);
            *(float4*)&Vs[swz(row, q4)] = *(const float4*)(vsrc + row*64 + q4*4);
        }
        __syncthreads();

        // ---- S = Q K^T (4x4 per thread) ----
        float s[4][4];
#pragma unroll
        for (int i = 0; i < 4; i++)
#pragma unroll
            for (int j = 0; j < 4; j++) s[i][j] = 0.f;

#pragma unroll 2
        for (int k4 = 0; k4 < 16; k4++) {
            float4 qreg[4];
#pragma unroll
            for (int i = 0; i < 4; i++)
                qreg[i] = *(const float4*)&Qs[swz(ty*4 + i, k4)];
#pragma unroll
            for (int j = 0; j < 4; j++) {
                float4 kr = *(const float4*)&Ks[swz(tx*4 + j, k4)];
#pragma unroll
                for (int i = 0; i < 4; i++) {
                    s[i][j] = fmaf(qreg[i].x, kr.x, s[i][j]);
                    s[i][j] = fmaf(qreg[i].y, kr.y, s[i][j]);
                    s[i][j] = fmaf(qreg[i].z, kr.z, s[i][j]);
                    s[i][j] = fmaf(qreg[i].w, kr.w, s[i][j]);
                }
            }
        }

        // ---- scale + causal/pad mask ----
        const int4 mv = *(const int4*)(mptr + k0 + tx*4);
        const int mvs[4] = {mv.x, mv.y, mv.z, mv.w};
        const bool diag = (kb == qb);
#pragma unroll
        for (int i = 0; i < 4; i++) {
            int rloc = ty*4 + i;
#pragma unroll
            for (int j = 0; j < 4; j++) {
                int cloc = tx*4 + j;
                bool ok = (mvs[j] != 0) && (!diag || cloc <= rloc);
                s[i][j] = ok ? s[i][j]*scale : -1e30f;
            }
        }

        // ---- online softmax (row-wise over 16 tx lanes) ----
#pragma unroll
        for (int i = 0; i < 4; i++) {
            float mloc = fmaxf(fmaxf(s[i][0], s[i][1]), fmaxf(s[i][2], s[i][3]));
#pragma unroll
            for (int off = 1; off < 16; off <<= 1)
                mloc = fmaxf(mloc, __shfl_xor_sync(0xffffffffu, mloc, off));
            float mnew = fmaxf(mrow[i], mloc);
            float al   = __expf(mrow[i] - mnew);
            float ls   = 0.f;
#pragma unroll
            for (int j = 0; j < 4; j++) {
                float p = __expf(s[i][j] - mnew);
                s[i][j] = p;
                ls += p;
            }
#pragma unroll
            for (int off = 1; off < 16; off <<= 1)
                ls += __shfl_xor_sync(0xffffffffu, ls, off);
            lrow[i] = lrow[i]*al + ls;
            mrow[i] = mnew;
#pragma unroll
            for (int j = 0; j < 4; j++) o[i][j] *= al;
        }

        __syncthreads();   // all S-readers of Ks done
        // ---- store P into Ks tile ----
#pragma unroll
        for (int i = 0; i < 4; i++)
            *(float4*)&Ks[swz(ty*4 + i, tx)] =
                make_float4(s[i][0], s[i][1], s[i][2], s[i][3]);
        __syncthreads();

        // ---- O += P V ----
#pragma unroll 2
        for (int c4 = 0; c4 < 16; c4++) {
            float4 preg[4];
#pragma unroll
            for (int i = 0; i < 4; i++)
                preg[i] = *(const float4*)&Ks[swz(ty*4 + i, c4)];
#pragma unroll
            for (int cc = 0; cc < 4; cc++) {
                float4 vr = *(const float4*)&Vs[swz(c4*4 + cc, tx)];
#pragma unroll
                for (int i = 0; i < 4; i++) {
                    float p = ((const float*)&preg[i])[cc];
                    o[i][0] = fmaf(p, vr.x, o[i][0]);
                    o[i][1] = fmaf(p, vr.y, o[i][1]);
                    o[i][2] = fmaf(p, vr.z, o[i][2]);
                    o[i][3] = fmaf(p, vr.w, o[i][3]);
                }
            }
        }
    }

    // ---- epilogue: normalize + write ----
#pragma unroll
    for (int i = 0; i < 4; i++) {
        float inv = 1.0f / lrow[i];
        float4 r4 = make_float4(o[i][0]*inv, o[i][1]*inv, o[i][2]*inv, o[i][3]*inv);
        *(float4*)(out + ((size_t)b*Tt + q0 + ty*4 + i)*HSd + tx*4) = r4;
    }
}

// ---------------------------------------------------------------------------
extern "C" void kernel_launch(void* const* d_in, const int* in_sizes, int n_in,
                              void* d_out, int out_size)
{
    const float* q_vec = (const float*)d_in[0];
    const float* k_vec = (const float*)d_in[1];
    const float* v_vec = (const float*)d_in[2];
    const int*   mask  = (const int*)  d_in[3];
    const float* Wq    = (const float*)d_in[4];
    const float* Wk    = (const float*)d_in[5];
    const float* Wv    = (const float*)d_in[6];
    float* out = (float*)d_out;

    proj_kernel<<<dim3(Mrows/32, 3), 256>>>(q_vec, k_vec, v_vec, Wq, Wk, Wv);
    attn_kernel<<<dim3(Tt/64, Bb), 256>>>(mask, out);
}

// round 2
// speedup vs baseline: 2.3083x; 2.3083x over previous
#include <cuda_runtime.h>
#include <cuda_bf16.h>
#include <cstdint>

#define Bb  8
#define Tt  2048
#define Cc  1024
#define HSd 64
#define Mrows (Bb*Tt)

// Projected q/k/v scratch (tf32-rounded fp32 bits), __device__ globals per rules.
__device__ float g_q[Mrows*HSd];
__device__ float g_k[Mrows*HSd];
__device__ float g_v[Mrows*HSd];

// round-to-nearest fp32 -> tf32 (bits in low 32, mantissa zero-padded)
__device__ __forceinline__ uint32_t f2tf(float f) {
    uint32_t u;
    asm("cvt.rna.tf32.f32 %0, %1;" : "=r"(u) : "f"(f));
    return u;
}

// m16n8k8 tf32 mma, C += A*B
__device__ __forceinline__ void mma8(float* c, const uint32_t* a, uint32_t b0, uint32_t b1) {
    asm volatile(
        "mma.sync.aligned.m16n8k8.row.col.f32.tf32.tf32.f32 "
        "{%0,%1,%2,%3},{%4,%5,%6,%7},{%8,%9},{%0,%1,%2,%3};"
        : "+f"(c[0]), "+f"(c[1]), "+f"(c[2]), "+f"(c[3])
        : "r"(a[0]), "r"(a[1]), "r"(a[2]), "r"(a[3]), "r"(b0), "r"(b1));
}

// ---------------------------------------------------------------------------
// Projection via tf32 mma: out[m][h] = in[m][:] @ W[:][h]
// CTA: 128 thr (4 warps), 64 rows x 64 cols, K-chunks of 64.
// As pitch 68 (A-frag reads conflict-free), Ws pitch 72 (B-frag reads c-free).
// Output rounded to tf32 (feeds the attention mma stage).
// ---------------------------------------------------------------------------
__global__ __launch_bounds__(128)
void proj_kernel(const float* __restrict__ qv, const float* __restrict__ kv,
                 const float* __restrict__ vv,
                 const float* __restrict__ Wq, const float* __restrict__ Wk,
                 const float* __restrict__ Wv)
{
    __shared__ float As[64*68];
    __shared__ float Ws[64*72];

    const float* __restrict__ in;
    const float* __restrict__ W;
    float* out;
    if (blockIdx.y == 0)      { in = qv; W = Wq; out = g_q; }
    else if (blockIdx.y == 1) { in = kv; W = Wk; out = g_k; }
    else                      { in = vv; W = Wv; out = g_v; }

    const int tid  = threadIdx.x;
    const int wid  = tid >> 5;
    const int lane = tid & 31;
    const int g    = lane >> 2;
    const int tig  = lane & 3;
    const int row0 = blockIdx.x * 64;
    const int m0w  = wid * 16;

    float acc[8][4];
#pragma unroll
    for (int n = 0; n < 8; n++)
#pragma unroll
        for (int j = 0; j < 4; j++) acc[n][j] = 0.f;

    for (int k0 = 0; k0 < Cc; k0 += 64) {
        __syncthreads();
#pragma unroll
        for (int i = tid; i < 1024; i += 128) {
            int r = i >> 4, c4 = (i & 15) << 2;
            float4 a = *(const float4*)(in + (size_t)(row0 + r)*Cc + k0 + c4);
            float4 w = *(const float4*)(W + (size_t)(k0 + r)*HSd + c4);
            As[r*68 + c4 + 0] = __uint_as_float(f2tf(a.x));
            As[r*68 + c4 + 1] = __uint_as_float(f2tf(a.y));
            As[r*68 + c4 + 2] = __uint_as_float(f2tf(a.z));
            As[r*68 + c4 + 3] = __uint_as_float(f2tf(a.w));
            Ws[r*72 + c4 + 0] = __uint_as_float(f2tf(w.x));
            Ws[r*72 + c4 + 1] = __uint_as_float(f2tf(w.y));
            Ws[r*72 + c4 + 2] = __uint_as_float(f2tf(w.z));
            Ws[r*72 + c4 + 3] = __uint_as_float(f2tf(w.w));
        }
        __syncthreads();

#pragma unroll
        for (int ks = 0; ks < 8; ks++) {
            uint32_t af[4];
            af[0] = __float_as_uint(As[(m0w + g    )*68 + 8*ks + tig    ]);
            af[1] = __float_as_uint(As[(m0w + g + 8)*68 + 8*ks + tig    ]);
            af[2] = __float_as_uint(As[(m0w + g    )*68 + 8*ks + tig + 4]);
            af[3] = __float_as_uint(As[(m0w + g + 8)*68 + 8*ks + tig + 4]);
#pragma unroll
            for (int n = 0; n < 8; n++) {
                uint32_t b0 = __float_as_uint(Ws[(8*ks + tig    )*72 + 8*n + g]);
                uint32_t b1 = __float_as_uint(Ws[(8*ks + tig + 4)*72 + 8*n + g]);
                mma8(acc[n], af, b0, b1);
            }
        }
    }

    // epilogue: tf32-round and store (feeds next mma stage)
#pragma unroll
    for (int n = 0; n < 8; n++) {
        float2 v0 = make_float2(__uint_as_float(f2tf(acc[n][0])),
                                __uint_as_float(f2tf(acc[n][1])));
        float2 v1 = make_float2(__uint_as_float(f2tf(acc[n][2])),
                                __uint_as_float(f2tf(acc[n][3])));
        *(float2*)(out + (size_t)(row0 + m0w + g    )*HSd + 8*n + 2*tig) = v0;
        *(float2*)(out + (size_t)(row0 + m0w + g + 8)*HSd + 8*n + 2*tig) = v1;
    }
}

// ---------------------------------------------------------------------------
// Flash attention with tf32 mma. CTA: 128 thr (4 warps); Q tile 64 rows
// (16/warp), K tile 64. Q fragments live in registers for the whole CTA.
// KP buffer (pitch 68): K tile, then reused for P. Vs pitch 72.
// All fragment LDS patterns are bank-conflict-free by pitch construction.
// ---------------------------------------------------------------------------
__global__ __launch_bounds__(128, 4)
void attn_kernel(const int* __restrict__ mask, float* __restrict__ out)
{
    __shared__ float KP[64*68];
    __shared__ float Vs[64*72];
    __shared__ int   msk[64];

    const int b   = blockIdx.y;
    const int qb  = (gridDim.x - 1) - blockIdx.x;   // longest first
    const int q0  = qb * 64;
    const int tid  = threadIdx.x;
    const int wid  = tid >> 5;
    const int lane = tid & 31;
    const int g    = lane >> 2;
    const int tig  = lane & 3;
    const int m0w  = wid * 16;

    // Q fragments: 16 rows x 64 head, 8 k-steps x 4 regs (already tf32-rounded)
    uint32_t qf[8][4];
    const float* qbase = g_q + (size_t)(b*Tt + q0 + m0w)*HSd;
#pragma unroll
    for (int k = 0; k < 8; k++) {
        qf[k][0] = __float_as_uint(qbase[(g    )*HSd + 8*k + tig    ]);
        qf[k][1] = __float_as_uint(qbase[(g + 8)*HSd + 8*k + tig    ]);
        qf[k][2] = __float_as_uint(qbase[(g    )*HSd + 8*k + tig + 4]);
        qf[k][3] = __float_as_uint(qbase[(g + 8)*HSd + 8*k + tig + 4]);
    }

    float o[8][4];
#pragma unroll
    for (int n = 0; n < 8; n++)
#pragma unroll
        for (int j = 0; j < 4; j++) o[n][j] = 0.f;
    float mr0 = -1e30f, mr1 = -1e30f, lr0 = 0.f, lr1 = 0.f;

    const float scale = 0.125f;   // HS^-0.5
    const int row0g = q0 + m0w + g;
    const int row1g = row0g + 8;

    for (int kb = 0; kb <= qb; kb++) {
        const int k0 = kb * 64;
        __syncthreads();   // prev tile's P/V readers done

        const float* kg = g_k + (size_t)(b*Tt + k0)*HSd;
        const float* vg = g_v + (size_t)(b*Tt + k0)*HSd;
#pragma unroll
        for (int i = tid; i < 1024; i += 128) {
            int r = i >> 4, c4 = (i & 15) << 2;
            *(float4*)&KP[r*68 + c4] = *(const float4*)(kg + r*HSd + c4);
            *(float4*)&Vs[r*72 + c4] = *(const float4*)(vg + r*HSd + c4);
        }
        if (tid < 64) msk[tid] = mask[b*Tt + k0 + tid];
        __syncthreads();

        // ---- S = Q K^T ----
        float s[8][4];
#pragma unroll
        for (int n = 0; n < 8; n++)
#pragma unroll
            for (int j = 0; j < 4; j++) s[n][j] = 0.f;
#pragma unroll
        for (int k = 0; k < 8; k++) {
#pragma unroll
            for (int n = 0; n < 8; n++) {
                uint32_t b0 = __float_as_uint(KP[(8*n + g)*68 + 8*k + tig    ]);
                uint32_t b1 = __float_as_uint(KP[(8*n + g)*68 + 8*k + tig + 4]);
                mma8(s[n], qf[k], b0, b1);
            }
        }

        // ---- scale + causal/pad mask ----
        const bool diag = (kb == qb);
#pragma unroll
        for (int n = 0; n < 8; n++) {
            int cl = 8*n + 2*tig;
            int2 mm = *(const int2*)&msk[cl];
            int c0 = k0 + cl, c1 = c0 + 1;
            bool v00 = (mm.x != 0) && (!diag || c0 <= row0g);
            bool v01 = (mm.y != 0) && (!diag || c1 <= row0g);
            bool v10 = (mm.x != 0) && (!diag || c0 <= row1g);
            bool v11 = (mm.y != 0) && (!diag || c1 <= row1g);
            s[n][0] = v00 ? s[n][0]*scale : -1e30f;
            s[n][1] = v01 ? s[n][1]*scale : -1e30f;
            s[n][2] = v10 ? s[n][2]*scale : -1e30f;
            s[n][3] = v11 ? s[n][3]*scale : -1e30f;
        }

        // ---- online softmax (rows g and g+8; cols spread over the quad) ----
        {
            float m0 = -1e30f, m1 = -1e30f;
#pragma unroll
            for (int n = 0; n < 8; n++) {
                m0 = fmaxf(m0, fmaxf(s[n][0], s[n][1]));
                m1 = fmaxf(m1, fmaxf(s[n][2], s[n][3]));
            }
#pragma unroll
            for (int off = 1; off < 4; off <<= 1) {
                m0 = fmaxf(m0, __shfl_xor_sync(0xffffffffu, m0, off));
                m1 = fmaxf(m1, __shfl_xor_sync(0xffffffffu, m1, off));
            }
            float mn0 = fmaxf(mr0, m0), mn1 = fmaxf(mr1, m1);
            float al0 = __expf(mr0 - mn0), al1 = __expf(mr1 - mn1);
            float ls0 = 0.f, ls1 = 0.f;
#pragma unroll
            for (int n = 0; n < 8; n++) {
                s[n][0] = __expf(s[n][0] - mn0);
                s[n][1] = __expf(s[n][1] - mn0);
                s[n][2] = __expf(s[n][2] - mn1);
                s[n][3] = __expf(s[n][3] - mn1);
                ls0 += s[n][0] + s[n][1];
                ls1 += s[n][2] + s[n][3];
            }
#pragma unroll
            for (int off = 1; off < 4; off <<= 1) {
                ls0 += __shfl_xor_sync(0xffffffffu, ls0, off);
                ls1 += __shfl_xor_sync(0xffffffffu, ls1, off);
            }
            lr0 = lr0*al0 + ls0;  mr0 = mn0;
            lr1 = lr1*al1 + ls1;  mr1 = mn1;
#pragma unroll
            for (int n = 0; n < 8; n++) {
                o[n][0] *= al0; o[n][1] *= al0;
                o[n][2] *= al1; o[n][3] *= al1;
            }
        }

        __syncthreads();   // all warps done reading K from KP
        // ---- P (tf32-rounded) into KP ----
#pragma unroll
        for (int n = 0; n < 8; n++) {
            float2 p0 = make_float2(__uint_as_float(f2tf(s[n][0])),
                                    __uint_as_float(f2tf(s[n][1])));
            float2 p1 = make_float2(__uint_as_float(f2tf(s[n][2])),
                                    __uint_as_float(f2tf(s[n][3])));
            *(float2*)&KP[(m0w + g    )*68 + 8*n + 2*tig] = p0;
            *(float2*)&KP[(m0w + g + 8)*68 + 8*n + 2*tig] = p1;
        }
        __syncthreads();

        // ---- O += P V ----
#pragma unroll
        for (int k = 0; k < 8; k++) {
            uint32_t af[4];
            af[0] = __float_as_uint(KP[(m0w + g    )*68 + 8*k + tig    ]);
            af[1] = __float_as_uint(KP[(m0w + g + 8)*68 + 8*k + tig    ]);
            af[2] = __float_as_uint(KP[(m0w + g    )*68 + 8*k + tig + 4]);
            af[3] = __float_as_uint(KP[(m0w + g + 8)*68 + 8*k + tig + 4]);
#pragma unroll
            for (int n = 0; n < 8; n++) {
                uint32_t b0 = __float_as_uint(Vs[(8*k + tig    )*72 + 8*n + g]);
                uint32_t b1 = __float_as_uint(Vs[(8*k + tig + 4)*72 + 8*n + g]);
                mma8(o[n], af, b0, b1);
            }
        }
    }

    // ---- epilogue ----
    const float inv0 = 1.0f / lr0, inv1 = 1.0f / lr1;
    float* obase = out + (size_t)(b*Tt + q0 + m0w)*HSd;
#pragma unroll
    for (int n = 0; n < 8; n++) {
        *(float2*)(obase + (g    )*HSd + 8*n + 2*tig) =
            make_float2(o[n][0]*inv0, o[n][1]*inv0);
        *(float2*)(obase + (g + 8)*HSd + 8*n + 2*tig) =
            make_float2(o[n][2]*inv1, o[n][3]*inv1);
    }
}

// ---------------------------------------------------------------------------
extern "C" void kernel_launch(void* const* d_in, const int* in_sizes, int n_in,
                              void* d_out, int out_size)
{
    const float* q_vec = (const float*)d_in[0];
    const float* k_vec = (const float*)d_in[1];
    const float* v_vec = (const float*)d_in[2];
    const int*   mask  = (const int*)  d_in[3];
    const float* Wq    = (const float*)d_in[4];
    const float* Wk    = (const float*)d_in[5];
    const float* Wv    = (const float*)d_in[6];
    float* out = (float*)d_out;

    proj_kernel<<<dim3(Mrows/64, 3), 128>>>(q_vec, k_vec, v_vec, Wq, Wk, Wv);
    attn_kernel<<<dim3(Tt/64, Bb), 128>>>(mask, out);
}

// round 3
// speedup vs baseline: 4.2694x; 1.8495x over previous
#include <cuda_runtime.h>
#include <cuda_bf16.h>
#include <cstdint>

#define Bb  8
#define Tt  2048
#define Cc  1024
#define HSd 64
#define Mrows (Bb*Tt)
#define NQT  32            // Q tiles per batch (Tt/64)
#define MAXCH 4            // max KV chunks per Q tile

// Projected q/k/v (tf32-rounded fp32 bits)
__device__ float g_q[Mrows*HSd];
__device__ float g_k[Mrows*HSd];
__device__ float g_v[Mrows*HSd];
// Split-KV partials: unnormalized O, row max (log2 domain), row sum
__device__ float g_pO[Bb*NQT*MAXCH*64*64];
__device__ float g_pm[Bb*NQT*MAXCH*64];
__device__ float g_pl[Bb*NQT*MAXCH*64];

__device__ __forceinline__ uint32_t f2tf(float f) {
    uint32_t u;
    asm("cvt.rna.tf32.f32 %0, %1;" : "=r"(u) : "f"(f));
    return u;
}
__device__ __forceinline__ float ex2(float x) {
    float r;
    asm("ex2.approx.ftz.f32 %0, %1;" : "=f"(r) : "f"(x));
    return r;
}
__device__ __forceinline__ void mma8(float* c, const uint32_t* a, uint32_t b0, uint32_t b1) {
    asm volatile(
        "mma.sync.aligned.m16n8k8.row.col.f32.tf32.tf32.f32 "
        "{%0,%1,%2,%3},{%4,%5,%6,%7},{%8,%9},{%0,%1,%2,%3};"
        : "+f"(c[0]), "+f"(c[1]), "+f"(c[2]), "+f"(c[3])
        : "r"(a[0]), "r"(a[1]), "r"(a[2]), "r"(a[3]), "r"(b0), "r"(b1));
}

// ---------------------------------------------------------------------------
// Projection, double-buffered. CTA: 128 thr, 64 rows x 64 cols, K-chunks of 32.
// As pitch 36 (A-frags conflict-free), Ws pitch 72 (B-frags conflict-free).
// ---------------------------------------------------------------------------
__global__ __launch_bounds__(128)
void proj_kernel(const float* __restrict__ qv, const float* __restrict__ kv,
                 const float* __restrict__ vv,
                 const float* __restrict__ Wq, const float* __restrict__ Wk,
                 const float* __restrict__ Wv)
{
    __shared__ float As[2][64*36];
    __shared__ float Ws[2][32*72];

    const float* __restrict__ in;
    const float* __restrict__ W;
    float* out;
    if (blockIdx.y == 0)      { in = qv; W = Wq; out = g_q; }
    else if (blockIdx.y == 1) { in = kv; W = Wk; out = g_k; }
    else                      { in = vv; W = Wv; out = g_v; }

    const int tid  = threadIdx.x;
    const int wid  = tid >> 5;
    const int lane = tid & 31;
    const int g    = lane >> 2;
    const int tig  = lane & 3;
    const int row0 = blockIdx.x * 64;
    const int m0w  = wid * 16;

    float4 pa[4], pw[4];

#define PROJ_LOAD(k0)                                                         \
    {                                                                         \
        _Pragma("unroll")                                                     \
        for (int j = 0; j < 4; j++) {                                         \
            int f = tid + 128*j;                                              \
            int r = f >> 3, c4 = (f & 7) << 2;                                \
            pa[j] = *(const float4*)(in + (size_t)(row0 + r)*Cc + (k0) + c4); \
        }                                                                     \
        _Pragma("unroll")                                                     \
        for (int j = 0; j < 4; j++) {                                         \
            int f = tid + 128*j;                                              \
            int r = f >> 4, c4 = (f & 15) << 2;                               \
            pw[j] = *(const float4*)(W + (size_t)((k0) + r)*HSd + c4);        \
        }                                                                     \
    }
#define PROJ_STS(buf)                                                         \
    {                                                                         \
        _Pragma("unroll")                                                     \
        for (int j = 0; j < 4; j++) {                                         \
            int f = tid + 128*j;                                              \
            int r = f >> 3, c4 = (f & 7) << 2;                                \
            As[buf][r*36 + c4 + 0] = __uint_as_float(f2tf(pa[j].x));          \
            As[buf][r*36 + c4 + 1] = __uint_as_float(f2tf(pa[j].y));          \
            As[buf][r*36 + c4 + 2] = __uint_as_float(f2tf(pa[j].z));          \
            As[buf][r*36 + c4 + 3] = __uint_as_float(f2tf(pa[j].w));          \
        }                                                                     \
        _Pragma("unroll")                                                     \
        for (int j = 0; j < 4; j++) {                                         \
            int f = tid + 128*j;                                              \
            int r = f >> 4, c4 = (f & 15) << 2;                               \
            Ws[buf][r*72 + c4 + 0] = __uint_as_float(f2tf(pw[j].x));          \
            Ws[buf][r*72 + c4 + 1] = __uint_as_float(f2tf(pw[j].y));          \
            Ws[buf][r*72 + c4 + 2] = __uint_as_float(f2tf(pw[j].z));          \
            Ws[buf][r*72 + c4 + 3] = __uint_as_float(f2tf(pw[j].w));          \
        }                                                                     \
    }

    float acc[8][4];
#pragma unroll
    for (int n = 0; n < 8; n++)
#pragma unroll
        for (int j = 0; j < 4; j++) acc[n][j] = 0.f;

    PROJ_LOAD(0);
    PROJ_STS(0);
    __syncthreads();

    for (int c = 0; c < 32; c++) {
        const int cur = c & 1;
        if (c < 31) PROJ_LOAD(32*(c+1));

#pragma unroll
        for (int ks = 0; ks < 4; ks++) {
            uint32_t af[4];
            af[0] = __float_as_uint(As[cur][(m0w + g    )*36 + 8*ks + tig    ]);
            af[1] = __float_as_uint(As[cur][(m0w + g + 8)*36 + 8*ks + tig    ]);
            af[2] = __float_as_uint(As[cur][(m0w + g    )*36 + 8*ks + tig + 4]);
            af[3] = __float_as_uint(As[cur][(m0w + g + 8)*36 + 8*ks + tig + 4]);
#pragma unroll
            for (int n = 0; n < 8; n++) {
                uint32_t b0 = __float_as_uint(Ws[cur][(8*ks + tig    )*72 + 8*n + g]);
                uint32_t b1 = __float_as_uint(Ws[cur][(8*ks + tig + 4)*72 + 8*n + g]);
                mma8(acc[n], af, b0, b1);
            }
        }
        if (c < 31) PROJ_STS(cur ^ 1);
        __syncthreads();
    }

#pragma unroll
    for (int n = 0; n < 8; n++) {
        float2 v0 = make_float2(__uint_as_float(f2tf(acc[n][0])),
                                __uint_as_float(f2tf(acc[n][1])));
        float2 v1 = make_float2(__uint_as_float(f2tf(acc[n][2])),
                                __uint_as_float(f2tf(acc[n][3])));
        *(float2*)(out + (size_t)(row0 + m0w + g    )*HSd + 8*n + 2*tig) = v0;
        *(float2*)(out + (size_t)(row0 + m0w + g + 8)*HSd + 8*n + 2*tig) = v1;
    }
#undef PROJ_LOAD
#undef PROJ_STS
}

// ---------------------------------------------------------------------------
// Split-KV flash attention. Each CTA: one 64-row Q tile x up to 8 KV tiles.
// Grid 640 = 8 batches x 80 (qb,chunk) pairs, heavy chunks first.
// 128 thr (4 warps); Q frags in registers; KP reused for P (warp-local rows).
// Softmax in log2 domain. Partials to scratch unless single-chunk.
// ---------------------------------------------------------------------------
__global__ __launch_bounds__(128, 4)
void attn_kernel(const int* __restrict__ mask, float* __restrict__ out)
{
    __shared__ float KP[64*68];
    __shared__ float Vs[64*72];
    __shared__ int   msk[64];

    const int i = blockIdx.x;
    const int b = i & 7;
    const int r = i >> 3;
    int qb, chunk;
    if (r < 32)      { qb = 24 + (r >> 2);       chunk = r & 3; }
    else if (r < 56) { int t = r - 32; qb = 16 + t/3; chunk = t - 3*(t/3); }
    else if (r < 72) { int t = r - 56; qb = 8 + (t >> 1); chunk = t & 1; }
    else             { qb = r - 72;              chunk = 0; }
    const int nch   = (qb + 8) >> 3;          // 1,2,3,4
    const int kb_lo = chunk * 8;
    const int kb_hi = min(kb_lo + 8, qb + 1);

    const int q0   = qb * 64;
    const int tid  = threadIdx.x;
    const int wid  = tid >> 5;
    const int lane = tid & 31;
    const int g    = lane >> 2;
    const int tig  = lane & 3;
    const int m0w  = wid * 16;

    // Q fragments (tf32 bits already)
    uint32_t qf[8][4];
    const float* qbase = g_q + (size_t)(b*Tt + q0 + m0w)*HSd;
#pragma unroll
    for (int k = 0; k < 8; k++) {
        qf[k][0] = __float_as_uint(qbase[(g    )*HSd + 8*k + tig    ]);
        qf[k][1] = __float_as_uint(qbase[(g + 8)*HSd + 8*k + tig    ]);
        qf[k][2] = __float_as_uint(qbase[(g    )*HSd + 8*k + tig + 4]);
        qf[k][3] = __float_as_uint(qbase[(g + 8)*HSd + 8*k + tig + 4]);
    }

    float o[8][4];
#pragma unroll
    for (int n = 0; n < 8; n++)
#pragma unroll
        for (int j = 0; j < 4; j++) o[n][j] = 0.f;
    float mr0 = -1e30f, mr1 = -1e30f, lr0 = 0.f, lr1 = 0.f;

    const float scale2 = 0.125f * 1.4426950408889634f;  // HS^-0.5 * log2(e)
    const int row0g = q0 + m0w + g;
    const int row1g = row0g + 8;

    for (int kb = kb_lo; kb < kb_hi; kb++) {
        const int k0 = kb * 64;
        __syncthreads();   // previous tile's K/V/msk readers done

        const float* kg = g_k + (size_t)(b*Tt + k0)*HSd;
        const float* vg = g_v + (size_t)(b*Tt + k0)*HSd;
#pragma unroll
        for (int t = tid; t < 1024; t += 128) {
            int rr = t >> 4, c4 = (t & 15) << 2;
            *(float4*)&KP[rr*68 + c4] = *(const float4*)(kg + rr*HSd + c4);
            *(float4*)&Vs[rr*72 + c4] = *(const float4*)(vg + rr*HSd + c4);
        }
        if (tid < 64) msk[tid] = mask[b*Tt + k0 + tid];
        __syncthreads();

        // ---- S = Q K^T ----
        float s[8][4];
#pragma unroll
        for (int n = 0; n < 8; n++)
#pragma unroll
            for (int j = 0; j < 4; j++) s[n][j] = 0.f;
#pragma unroll
        for (int k = 0; k < 8; k++) {
#pragma unroll
            for (int n = 0; n < 8; n++) {
                uint32_t b0 = __float_as_uint(KP[(8*n + g)*68 + 8*k + tig    ]);
                uint32_t b1 = __float_as_uint(KP[(8*n + g)*68 + 8*k + tig + 4]);
                mma8(s[n], qf[k], b0, b1);
            }
        }

        // ---- scale (log2 domain) + causal/pad mask ----
        const bool diag = (kb == qb);
#pragma unroll
        for (int n = 0; n < 8; n++) {
            int cl = 8*n + 2*tig;
            int2 mm = *(const int2*)&msk[cl];
            int c0 = k0 + cl, c1 = c0 + 1;
            bool v00 = (mm.x != 0) && (!diag || c0 <= row0g);
            bool v01 = (mm.y != 0) && (!diag || c1 <= row0g);
            bool v10 = (mm.x != 0) && (!diag || c0 <= row1g);
            bool v11 = (mm.y != 0) && (!diag || c1 <= row1g);
            s[n][0] = v00 ? s[n][0]*scale2 : -1e30f;
            s[n][1] = v01 ? s[n][1]*scale2 : -1e30f;
            s[n][2] = v10 ? s[n][2]*scale2 : -1e30f;
            s[n][3] = v11 ? s[n][3]*scale2 : -1e30f;
        }

        // ---- online softmax, base-2 ----
        {
            float m0 = -1e30f, m1 = -1e30f;
#pragma unroll
            for (int n = 0; n < 8; n++) {
                m0 = fmaxf(m0, fmaxf(s[n][0], s[n][1]));
                m1 = fmaxf(m1, fmaxf(s[n][2], s[n][3]));
            }
#pragma unroll
            for (int off = 1; off < 4; off <<= 1) {
                m0 = fmaxf(m0, __shfl_xor_sync(0xffffffffu, m0, off));
                m1 = fmaxf(m1, __shfl_xor_sync(0xffffffffu, m1, off));
            }
            float mn0 = fmaxf(mr0, m0), mn1 = fmaxf(mr1, m1);
            float al0 = ex2(mr0 - mn0), al1 = ex2(mr1 - mn1);
            float ls0 = 0.f, ls1 = 0.f;
#pragma unroll
            for (int n = 0; n < 8; n++) {
                s[n][0] = ex2(s[n][0] - mn0);
                s[n][1] = ex2(s[n][1] - mn0);
                s[n][2] = ex2(s[n][2] - mn1);
                s[n][3] = ex2(s[n][3] - mn1);
                ls0 += s[n][0] + s[n][1];
                ls1 += s[n][2] + s[n][3];
            }
#pragma unroll
            for (int off = 1; off < 4; off <<= 1) {
                ls0 += __shfl_xor_sync(0xffffffffu, ls0, off);
                ls1 += __shfl_xor_sync(0xffffffffu, ls1, off);
            }
            lr0 = lr0*al0 + ls0;  mr0 = mn0;
            lr1 = lr1*al1 + ls1;  mr1 = mn1;
#pragma unroll
            for (int n = 0; n < 8; n++) {
                o[n][0] *= al0; o[n][1] *= al0;
                o[n][2] *= al1; o[n][3] *= al1;
            }
        }

        __syncthreads();   // all warps done reading K rows of KP
        // ---- P (tf32) into own rows of KP; warp-local visibility only ----
#pragma unroll
        for (int n = 0; n < 8; n++) {
            float2 p0 = make_float2(__uint_as_float(f2tf(s[n][0])),
                                    __uint_as_float(f2tf(s[n][1])));
            float2 p1 = make_float2(__uint_as_float(f2tf(s[n][2])),
                                    __uint_as_float(f2tf(s[n][3])));
            *(float2*)&KP[(m0w + g    )*68 + 8*n + 2*tig] = p0;
            *(float2*)&KP[(m0w + g + 8)*68 + 8*n + 2*tig] = p1;
        }
        __syncwarp();

        // ---- O += P V ----
#pragma unroll
        for (int k = 0; k < 8; k++) {
            uint32_t af[4];
            af[0] = __float_as_uint(KP[(m0w + g    )*68 + 8*k + tig    ]);
            af[1] = __float_as_uint(KP[(m0w + g + 8)*68 + 8*k + tig    ]);
            af[2] = __float_as_uint(KP[(m0w + g    )*68 + 8*k + tig + 4]);
            af[3] = __float_as_uint(KP[(m0w + g + 8)*68 + 8*k + tig + 4]);
#pragma unroll
            for (int n = 0; n < 8; n++) {
                uint32_t b0 = __float_as_uint(Vs[(8*k + tig    )*72 + 8*n + g]);
                uint32_t b1 = __float_as_uint(Vs[(8*k + tig + 4)*72 + 8*n + g]);
                mma8(o[n], af, b0, b1);
            }
        }
    }

    // ---- epilogue ----
    if (nch == 1) {
        const float inv0 = 1.0f / lr0, inv1 = 1.0f / lr1;
        float* obase = out + (size_t)(b*Tt + q0 + m0w)*HSd;
#pragma unroll
        for (int n = 0; n < 8; n++) {
            *(float2*)(obase + (g    )*HSd + 8*n + 2*tig) =
                make_float2(o[n][0]*inv0, o[n][1]*inv0);
            *(float2*)(obase + (g + 8)*HSd + 8*n + 2*tig) =
                make_float2(o[n][2]*inv1, o[n][3]*inv1);
        }
    } else {
        const size_t idx = (size_t)((b*NQT + qb)*MAXCH + chunk);
        float* pO = g_pO + idx*4096;
#pragma unroll
        for (int n = 0; n < 8; n++) {
            *(float2*)&pO[(m0w + g    )*64 + 8*n + 2*tig] =
                make_float2(o[n][0], o[n][1]);
            *(float2*)&pO[(m0w + g + 8)*64 + 8*n + 2*tig] =
                make_float2(o[n][2], o[n][3]);
        }
        if (tig == 0) {
            g_pm[idx*64 + m0w + g    ] = mr0;
            g_pl[idx*64 + m0w + g    ] = lr0;
            g_pm[idx*64 + m0w + g + 8] = mr1;
            g_pl[idx*64 + m0w + g + 8] = lr1;
        }
    }
}

// ---------------------------------------------------------------------------
// Combine partials for qb >= 8 (2..4 chunks). Grid (24, 8) x 128 thr.
// ---------------------------------------------------------------------------
__global__ __launch_bounds__(128)
void combine_kernel(float* __restrict__ out)
{
    const int qb  = 8 + blockIdx.x;
    const int b   = blockIdx.y;
    const int nch = (qb + 8) >> 3;
    const int t   = threadIdx.x;
    const int row = t >> 1;
    const int half = (t & 1) * 32;
    const int base = (b*NQT + qb)*MAXCH;

    float mg = -1e30f;
    for (int i = 0; i < nch; i++)
        mg = fmaxf(mg, g_pm[(base + i)*64 + row]);

    float l = 0.f;
    float4 acc[8];
#pragma unroll
    for (int j = 0; j < 8; j++) acc[j] = make_float4(0.f, 0.f, 0.f, 0.f);

    for (int i = 0; i < nch; i++) {
        float w = ex2(g_pm[(base + i)*64 + row] - mg);
        l += w * g_pl[(base + i)*64 + row];
        const float4* src = (const float4*)&g_pO[(size_t)(base + i)*4096 + row*64 + half];
#pragma unroll
        for (int j = 0; j < 8; j++) {
            float4 v = src[j];
            acc[j].x += w*v.x; acc[j].y += w*v.y;
            acc[j].z += w*v.z; acc[j].w += w*v.w;
        }
    }

    const float inv = 1.0f / l;
    float4* dst = (float4*)(out + (size_t)(b*Tt + qb*64 + row)*HSd + half);
#pragma unroll
    for (int j = 0; j < 8; j++)
        dst[j] = make_float4(acc[j].x*inv, acc[j].y*inv, acc[j].z*inv, acc[j].w*inv);
}

// ---------------------------------------------------------------------------
extern "C" void kernel_launch(void* const* d_in, const int* in_sizes, int n_in,
                              void* d_out, int out_size)
{
    const float* q_vec = (const float*)d_in[0];
    const float* k_vec = (const float*)d_in[1];
    const float* v_vec = (const float*)d_in[2];
    const int*   mask  = (const int*)  d_in[3];
    const float* Wq    = (const float*)d_in[4];
    const float* Wk    = (const float*)d_in[5];
    const float* Wv    = (const float*)d_in[6];
    float* out = (float*)d_out;

    proj_kernel<<<dim3(Mrows/64, 3), 128>>>(q_vec, k_vec, v_vec, Wq, Wk, Wv);
    attn_kernel<<<640, 128>>>(mask, out);
    combine_kernel<<<dim3(24, 8), 128>>>(out);
}

// round 4
// speedup vs baseline: 4.2910x; 1.0051x over previous
#include <cuda_runtime.h>
#include <cuda_bf16.h>
#include <cstdint>

#define Bb  8
#define Tt  2048
#define Cc  1024
#define HSd 64
#define Mrows (Bb*Tt)
#define NQT  32            // Q tiles per batch (Tt/64)
#define MAXCH 4            // max KV chunks per Q tile

// Projected q/k/v (tf32-rounded fp32 bits)
__device__ float g_q[Mrows*HSd];
__device__ float g_k[Mrows*HSd];
__device__ float g_v[Mrows*HSd];
// Split-KV partials: unnormalized O, row max (log2 domain), row sum
__device__ float g_pO[Bb*NQT*MAXCH*64*64];
__device__ float g_pm[Bb*NQT*MAXCH*64];
__device__ float g_pl[Bb*NQT*MAXCH*64];

__device__ __forceinline__ uint32_t f2tf(float f) {
    uint32_t u;
    asm("cvt.rna.tf32.f32 %0, %1;" : "=r"(u) : "f"(f));
    return u;
}
__device__ __forceinline__ float ex2(float x) {
    float r;
    asm("ex2.approx.ftz.f32 %0, %1;" : "=f"(r) : "f"(x));
    return r;
}
__device__ __forceinline__ void mma8(float* c, const uint32_t* a, uint32_t b0, uint32_t b1) {
    asm volatile(
        "mma.sync.aligned.m16n8k8.row.col.f32.tf32.tf32.f32 "
        "{%0,%1,%2,%3},{%4,%5,%6,%7},{%8,%9},{%0,%1,%2,%3};"
        : "+f"(c[0]), "+f"(c[1]), "+f"(c[2]), "+f"(c[3])
        : "r"(a[0]), "r"(a[1]), "r"(a[2]), "r"(a[3]), "r"(b0), "r"(b1));
}

// ---------------------------------------------------------------------------
// Projection, double-buffered. CTA: 128 thr, 64 rows x 64 cols, K-chunks of 32.
// As pitch 36 (A-frags conflict-free), Ws pitch 72 (B-frags conflict-free).
// ---------------------------------------------------------------------------
__global__ __launch_bounds__(128)
void proj_kernel(const float* __restrict__ qv, const float* __restrict__ kv,
                 const float* __restrict__ vv,
                 const float* __restrict__ Wq, const float* __restrict__ Wk,
                 const float* __restrict__ Wv)
{
    __shared__ float As[2][64*36];
    __shared__ float Ws[2][32*72];

    const float* __restrict__ in;
    const float* __restrict__ W;
    float* out;
    if (blockIdx.y == 0)      { in = qv; W = Wq; out = g_q; }
    else if (blockIdx.y == 1) { in = kv; W = Wk; out = g_k; }
    else                      { in = vv; W = Wv; out = g_v; }

    const int tid  = threadIdx.x;
    const int wid  = tid >> 5;
    const int lane = tid & 31;
    const int g    = lane >> 2;
    const int tig  = lane & 3;
    const int row0 = blockIdx.x * 64;
    const int m0w  = wid * 16;

    float4 pa[4], pw[4];

#define PROJ_LOAD(k0)                                                         \
    {                                                                         \
        _Pragma("unroll")                                                     \
        for (int j = 0; j < 4; j++) {                                         \
            int f = tid + 128*j;                                              \
            int r = f >> 3, c4 = (f & 7) << 2;                                \
            pa[j] = *(const float4*)(in + (size_t)(row0 + r)*Cc + (k0) + c4); \
        }                                                                     \
        _Pragma("unroll")                                                     \
        for (int j = 0; j < 4; j++) {                                         \
            int f = tid + 128*j;                                              \
            int r = f >> 4, c4 = (f & 15) << 2;                               \
            pw[j] = *(const float4*)(W + (size_t)((k0) + r)*HSd + c4);        \
        }                                                                     \
    }
#define PROJ_STS(buf)                                                         \
    {                                                                         \
        _Pragma("unroll")                                                     \
        for (int j = 0; j < 4; j++) {                                         \
            int f = tid + 128*j;                                              \
            int r = f >> 3, c4 = (f & 7) << 2;                                \
            As[buf][r*36 + c4 + 0] = __uint_as_float(f2tf(pa[j].x));          \
            As[buf][r*36 + c4 + 1] = __uint_as_float(f2tf(pa[j].y));          \
            As[buf][r*36 + c4 + 2] = __uint_as_float(f2tf(pa[j].z));          \
            As[buf][r*36 + c4 + 3] = __uint_as_float(f2tf(pa[j].w));          \
        }                                                                     \
        _Pragma("unroll")                                                     \
        for (int j = 0; j < 4; j++) {                                         \
            int f = tid + 128*j;                                              \
            int r = f >> 4, c4 = (f & 15) << 2;                               \
            Ws[buf][r*72 + c4 + 0] = __uint_as_float(f2tf(pw[j].x));          \
            Ws[buf][r*72 + c4 + 1] = __uint_as_float(f2tf(pw[j].y));          \
            Ws[buf][r*72 + c4 + 2] = __uint_as_float(f2tf(pw[j].z));          \
            Ws[buf][r*72 + c4 + 3] = __uint_as_float(f2tf(pw[j].w));          \
        }                                                                     \
    }

    float acc[8][4];
#pragma unroll
    for (int n = 0; n < 8; n++)
#pragma unroll
        for (int j = 0; j < 4; j++) acc[n][j] = 0.f;

    PROJ_LOAD(0);
    PROJ_STS(0);
    __syncthreads();

    for (int c = 0; c < 32; c++) {
        const int cur = c & 1;
        if (c < 31) PROJ_LOAD(32*(c+1));

#pragma unroll
        for (int ks = 0; ks < 4; ks++) {
            uint32_t af[4];
            af[0] = __float_as_uint(As[cur][(m0w + g    )*36 + 8*ks + tig    ]);
            af[1] = __float_as_uint(As[cur][(m0w + g + 8)*36 + 8*ks + tig    ]);
            af[2] = __float_as_uint(As[cur][(m0w + g    )*36 + 8*ks + tig + 4]);
            af[3] = __float_as_uint(As[cur][(m0w + g + 8)*36 + 8*ks + tig + 4]);
#pragma unroll
            for (int n = 0; n < 8; n++) {
                uint32_t b0 = __float_as_uint(Ws[cur][(8*ks + tig    )*72 + 8*n + g]);
                uint32_t b1 = __float_as_uint(Ws[cur][(8*ks + tig + 4)*72 + 8*n + g]);
                mma8(acc[n], af, b0, b1);
            }
        }
        if (c < 31) PROJ_STS(cur ^ 1);
        __syncthreads();
    }

#pragma unroll
    for (int n = 0; n < 8; n++) {
        float2 v0 = make_float2(__uint_as_float(f2tf(acc[n][0])),
                                __uint_as_float(f2tf(acc[n][1])));
        float2 v1 = make_float2(__uint_as_float(f2tf(acc[n][2])),
                                __uint_as_float(f2tf(acc[n][3])));
        *(float2*)(out + (size_t)(row0 + m0w + g    )*HSd + 8*n + 2*tig) = v0;
        *(float2*)(out + (size_t)(row0 + m0w + g + 8)*HSd + 8*n + 2*tig) = v1;
    }
#undef PROJ_LOAD
#undef PROJ_STS
}

// ---------------------------------------------------------------------------
// Split-KV flash attention. Each CTA: one 64-row Q tile x up to 8 KV tiles.
// Grid 640 = 8 batches x 80 (qb,chunk) pairs, heavy chunks first.
// 128 thr (4 warps); Q frags in registers; KP reused for P (warp-local rows).
// Softmax in log2 domain. Partials to scratch unless single-chunk.
// ---------------------------------------------------------------------------
__global__ __launch_bounds__(128, 4)
void attn_kernel(const int* __restrict__ mask, float* __restrict__ out)
{
    __shared__ float KP[64*68];
    __shared__ float Vs[64*72];
    __shared__ int   msk[64];

    const int i = blockIdx.x;
    const int b = i & 7;
    const int r = i >> 3;
    int qb, chunk;
    if (r < 32)      { qb = 24 + (r >> 2);       chunk = r & 3; }
    else if (r < 56) { int t = r - 32; qb = 16 + t/3; chunk = t - 3*(t/3); }
    else if (r < 72) { int t = r - 56; qb = 8 + (t >> 1); chunk = t & 1; }
    else             { qb = r - 72;              chunk = 0; }
    const int nch   = (qb + 8) >> 3;          // 1,2,3,4
    const int kb_lo = chunk * 8;
    const int kb_hi = min(kb_lo + 8, qb + 1);

    const int q0   = qb * 64;
    const int tid  = threadIdx.x;
    const int wid  = tid >> 5;
    const int lane = tid & 31;
    const int g    = lane >> 2;
    const int tig  = lane & 3;
    const int m0w  = wid * 16;

    // Q fragments (tf32 bits already)
    uint32_t qf[8][4];
    const float* qbase = g_q + (size_t)(b*Tt + q0 + m0w)*HSd;
#pragma unroll
    for (int k = 0; k < 8; k++) {
        qf[k][0] = __float_as_uint(qbase[(g    )*HSd + 8*k + tig    ]);
        qf[k][1] = __float_as_uint(qbase[(g + 8)*HSd + 8*k + tig    ]);
        qf[k][2] = __float_as_uint(qbase[(g    )*HSd + 8*k + tig + 4]);
        qf[k][3] = __float_as_uint(qbase[(g + 8)*HSd + 8*k + tig + 4]);
    }

    float o[8][4];
#pragma unroll
    for (int n = 0; n < 8; n++)
#pragma unroll
        for (int j = 0; j < 4; j++) o[n][j] = 0.f;
    float mr0 = -1e30f, mr1 = -1e30f, lr0 = 0.f, lr1 = 0.f;

    const float scale2 = 0.125f * 1.4426950408889634f;  // HS^-0.5 * log2(e)
    const int row0g = q0 + m0w + g;
    const int row1g = row0g + 8;

    for (int kb = kb_lo; kb < kb_hi; kb++) {
        const int k0 = kb * 64;
        __syncthreads();   // previous tile's K/V/msk readers done

        const float* kg = g_k + (size_t)(b*Tt + k0)*HSd;
        const float* vg = g_v + (size_t)(b*Tt + k0)*HSd;
#pragma unroll
        for (int t = tid; t < 1024; t += 128) {
            int rr = t >> 4, c4 = (t & 15) << 2;
            *(float4*)&KP[rr*68 + c4] = *(const float4*)(kg + rr*HSd + c4);
            *(float4*)&Vs[rr*72 + c4] = *(const float4*)(vg + rr*HSd + c4);
        }
        if (tid < 64) msk[tid] = mask[b*Tt + k0 + tid];
        __syncthreads();

        // ---- S = Q K^T ----
        float s[8][4];
#pragma unroll
        for (int n = 0; n < 8; n++)
#pragma unroll
            for (int j = 0; j < 4; j++) s[n][j] = 0.f;
#pragma unroll
        for (int k = 0; k < 8; k++) {
#pragma unroll
            for (int n = 0; n < 8; n++) {
                uint32_t b0 = __float_as_uint(KP[(8*n + g)*68 + 8*k + tig    ]);
                uint32_t b1 = __float_as_uint(KP[(8*n + g)*68 + 8*k + tig + 4]);
                mma8(s[n], qf[k], b0, b1);
            }
        }

        // ---- scale (log2 domain) + causal/pad mask ----
        const bool diag = (kb == qb);
#pragma unroll
        for (int n = 0; n < 8; n++) {
            int cl = 8*n + 2*tig;
            int2 mm = *(const int2*)&msk[cl];
            int c0 = k0 + cl, c1 = c0 + 1;
            bool v00 = (mm.x != 0) && (!diag || c0 <= row0g);
            bool v01 = (mm.y != 0) && (!diag || c1 <= row0g);
            bool v10 = (mm.x != 0) && (!diag || c0 <= row1g);
            bool v11 = (mm.y != 0) && (!diag || c1 <= row1g);
            s[n][0] = v00 ? s[n][0]*scale2 : -1e30f;
            s[n][1] = v01 ? s[n][1]*scale2 : -1e30f;
            s[n][2] = v10 ? s[n][2]*scale2 : -1e30f;
            s[n][3] = v11 ? s[n][3]*scale2 : -1e30f;
        }

        // ---- online softmax, base-2 ----
        {
            float m0 = -1e30f, m1 = -1e30f;
#pragma unroll
            for (int n = 0; n < 8; n++) {
                m0 = fmaxf(m0, fmaxf(s[n][0], s[n][1]));
                m1 = fmaxf(m1, fmaxf(s[n][2], s[n][3]));
            }
#pragma unroll
            for (int off = 1; off < 4; off <<= 1) {
                m0 = fmaxf(m0, __shfl_xor_sync(0xffffffffu, m0, off));
                m1 = fmaxf(m1, __shfl_xor_sync(0xffffffffu, m1, off));
            }
            float mn0 = fmaxf(mr0, m0), mn1 = fmaxf(mr1, m1);
            float al0 = ex2(mr0 - mn0), al1 = ex2(mr1 - mn1);
            float ls0 = 0.f, ls1 = 0.f;
#pragma unroll
            for (int n = 0; n < 8; n++) {
                s[n][0] = ex2(s[n][0] - mn0);
                s[n][1] = ex2(s[n][1] - mn0);
                s[n][2] = ex2(s[n][2] - mn1);
                s[n][3] = ex2(s[n][3] - mn1);
                ls0 += s[n][0] + s[n][1];
                ls1 += s[n][2] + s[n][3];
            }
#pragma unroll
            for (int off = 1; off < 4; off <<= 1) {
                ls0 += __shfl_xor_sync(0xffffffffu, ls0, off);
                ls1 += __shfl_xor_sync(0xffffffffu, ls1, off);
            }
            lr0 = lr0*al0 + ls0;  mr0 = mn0;
            lr1 = lr1*al1 + ls1;  mr1 = mn1;
#pragma unroll
            for (int n = 0; n < 8; n++) {
                o[n][0] *= al0; o[n][1] *= al0;
                o[n][2] *= al1; o[n][3] *= al1;
            }
        }

        __syncthreads();   // all warps done reading K rows of KP
        // ---- P (tf32) into own rows of KP; warp-local visibility only ----
#pragma unroll
        for (int n = 0; n < 8; n++) {
            float2 p0 = make_float2(__uint_as_float(f2tf(s[n][0])),
                                    __uint_as_float(f2tf(s[n][1])));
            float2 p1 = make_float2(__uint_as_float(f2tf(s[n][2])),
                                    __uint_as_float(f2tf(s[n][3])));
            *(float2*)&KP[(m0w + g    )*68 + 8*n + 2*tig] = p0;
            *(float2*)&KP[(m0w + g + 8)*68 + 8*n + 2*tig] = p1;
        }
        __syncwarp();

        // ---- O += P V ----
#pragma unroll
        for (int k = 0; k < 8; k++) {
            uint32_t af[4];
            af[0] = __float_as_uint(KP[(m0w + g    )*68 + 8*k + tig    ]);
            af[1] = __float_as_uint(KP[(m0w + g + 8)*68 + 8*k + tig    ]);
            af[2] = __float_as_uint(KP[(m0w + g    )*68 + 8*k + tig + 4]);
            af[3] = __float_as_uint(KP[(m0w + g + 8)*68 + 8*k + tig + 4]);
#pragma unroll
            for (int n = 0; n < 8; n++) {
                uint32_t b0 = __float_as_uint(Vs[(8*k + tig    )*72 + 8*n + g]);
                uint32_t b1 = __float_as_uint(Vs[(8*k + tig + 4)*72 + 8*n + g]);
                mma8(o[n], af, b0, b1);
            }
        }
    }

    // ---- epilogue ----
    if (nch == 1) {
        const float inv0 = 1.0f / lr0, inv1 = 1.0f / lr1;
        float* obase = out + (size_t)(b*Tt + q0 + m0w)*HSd;
#pragma unroll
        for (int n = 0; n < 8; n++) {
            *(float2*)(obase + (g    )*HSd + 8*n + 2*tig) =
                make_float2(o[n][0]*inv0, o[n][1]*inv0);
            *(float2*)(obase + (g + 8)*HSd + 8*n + 2*tig) =
                make_float2(o[n][2]*inv1, o[n][3]*inv1);
        }
    } else {
        const size_t idx = (size_t)((b*NQT + qb)*MAXCH + chunk);
        float* pO = g_pO + idx*4096;
#pragma unroll
        for (int n = 0; n < 8; n++) {
            *(float2*)&pO[(m0w + g    )*64 + 8*n + 2*tig] =
                make_float2(o[n][0], o[n][1]);
            *(float2*)&pO[(m0w + g + 8)*64 + 8*n + 2*tig] =
                make_float2(o[n][2], o[n][3]);
        }
        if (tig == 0) {
            g_pm[idx*64 + m0w + g    ] = mr0;
            g_pl[idx*64 + m0w + g    ] = lr0;
            g_pm[idx*64 + m0w + g + 8] = mr1;
            g_pl[idx*64 + m0w + g + 8] = lr1;
        }
    }
}

// ---------------------------------------------------------------------------
// Combine partials for qb >= 8 (2..4 chunks). Grid (24, 8) x 128 thr.
// ---------------------------------------------------------------------------
__global__ __launch_bounds__(128)
void combine_kernel(float* __restrict__ out)
{
    const int qb  = 8 + blockIdx.x;
    const int b   = blockIdx.y;
    const int nch = (qb + 8) >> 3;
    const int t   = threadIdx.x;
    const int row = t >> 1;
    const int half = (t & 1) * 32;
    const int base = (b*NQT + qb)*MAXCH;

    float mg = -1e30f;
    for (int i = 0; i < nch; i++)
        mg = fmaxf(mg, g_pm[(base + i)*64 + row]);

    float l = 0.f;
    float4 acc[8];
#pragma unroll
    for (int j = 0; j < 8; j++) acc[j] = make_float4(0.f, 0.f, 0.f, 0.f);

    for (int i = 0; i < nch; i++) {
        float w = ex2(g_pm[(base + i)*64 + row] - mg);
        l += w * g_pl[(base + i)*64 + row];
        const float4* src = (const float4*)&g_pO[(size_t)(base + i)*4096 + row*64 + half];
#pragma unroll
        for (int j = 0; j < 8; j++) {
            float4 v = src[j];
            acc[j].x += w*v.x; acc[j].y += w*v.y;
            acc[j].z += w*v.z; acc[j].w += w*v.w;
        }
    }

    const float inv = 1.0f / l;
    float4* dst = (float4*)(out + (size_t)(b*Tt + qb*64 + row)*HSd + half);
#pragma unroll
    for (int j = 0; j < 8; j++)
        dst[j] = make_float4(acc[j].x*inv, acc[j].y*inv, acc[j].z*inv, acc[j].w*inv);
}

// ---------------------------------------------------------------------------
extern "C" void kernel_launch(void* const* d_in, const int* in_sizes, int n_in,
                              void* d_out, int out_size)
{
    const float* q_vec = (const float*)d_in[0];
    const float* k_vec = (const float*)d_in[1];
    const float* v_vec = (const float*)d_in[2];
    const int*   mask  = (const int*)  d_in[3];
    const float* Wq    = (const float*)d_in[4];
    const float* Wk    = (const float*)d_in[5];
    const float* Wv    = (const float*)d_in[6];
    float* out = (float*)d_out;

    proj_kernel<<<dim3(Mrows/64, 3), 128>>>(q_vec, k_vec, v_vec, Wq, Wk, Wv);
    attn_kernel<<<640, 128>>>(mask, out);
    combine_kernel<<<dim3(24, 8), 128>>>(out);
}